// round 1
// baseline (speedup 1.0000x reference)
#include <cuda_runtime.h>
#include <cuda_bf16.h>

// Problem constants
#define Bn   16
#define Nn   4096
#define Mn   1024
#define C1n  128
#define C2n  256
#define CINn 384
#define H1n  256
#define H2n  128

#define TN   64   // n-tile
#define MC   32   // m chunk

// scratch: interpolated features [B][C2][N]
__device__ float g_interp[(size_t)Bn * C2n * Nn];

// ---------------- Kernel 1: inverse-distance interpolation ----------------
// grid (N/TN, B), 256 threads. Block computes interp[b][0..255][n0..n0+63].
// SMEM layout (floats):
//   s_x2   [0 .. 3072)            xyz2 for batch (AoS, m*3+d)
//   s_p2   [3072 .. 11392)        p2 chunk [MC][260]  (reused as s_out [128][65] in epilogue)
//   s_inv  [11392 .. 13440)       inv chunk [MC][64]
//   s_dsum [13440 .. 13696)       [4][64]
//   s_den  [13696 .. 13760)       [64]
#define ISM_FLOATS 13760
#define ISM_BYTES  (ISM_FLOATS * 4)

__global__ __launch_bounds__(256, 2)
void interp_kernel(const float* __restrict__ xyz1,
                   const float* __restrict__ xyz2,
                   const float* __restrict__ p2)
{
    extern __shared__ float sm[];
    float* s_x2   = sm;
    float* s_p2   = sm + 3072;        // [MC][260]
    float* s_inv  = sm + 11392;       // [MC][64]
    float* s_dsum = sm + 13440;       // [4][64]
    float* s_den  = sm + 13696;       // [64]

    const int b      = blockIdx.y;
    const int n_base = blockIdx.x * TN;
    const int tid    = threadIdx.x;

    // preload xyz2 for this batch (12KB)
    for (int i = tid; i < Mn * 3; i += 256)
        s_x2[i] = xyz2[(size_t)b * Mn * 3 + i];

    // fill-phase identity: each thread owns one n, 8 m's per chunk
    const int fn  = tid & 63;          // n for inv-fill
    const int fmg = tid >> 6;          // m-group 0..3
    const float x1a = xyz1[((size_t)b * Nn + n_base + fn) * 3 + 0];
    const float x1b = xyz1[((size_t)b * Nn + n_base + fn) * 3 + 1];
    const float x1c = xyz1[((size_t)b * Nn + n_base + fn) * 3 + 2];

    // compute-phase identity: 8n x 8c register tile
    const int ct = tid & 31;           // c-group: c0 = 8*ct
    const int nt = tid >> 5;           // n-group: n0 = 8*nt
    const int lane = tid & 31, w = tid >> 5;

    float acc[8][8];
    #pragma unroll
    for (int i = 0; i < 8; i++)
        #pragma unroll
        for (int j = 0; j < 8; j++) acc[i][j] = 0.f;

    float dsum = 0.f;

    for (int mc = 0; mc < Mn / MC; mc++) {
        const int m0 = mc * MC;
        __syncthreads();   // previous compute done reading smem

        // --- fill inv chunk + denom partials ---
        #pragma unroll
        for (int i = 0; i < 8; i++) {
            const int m = fmg * 8 + i;
            const float dx = x1a - s_x2[(m0 + m) * 3 + 0];
            const float dy = x1b - s_x2[(m0 + m) * 3 + 1];
            const float dz = x1c - s_x2[(m0 + m) * 3 + 2];
            const float d2 = dx * dx + dy * dy + dz * dz;
            const float inv = rsqrtf(d2 + 1e-16f);
            s_inv[m * 64 + fn] = inv;
            dsum += inv;
        }

        // --- stage p2 chunk transposed: s_p2[m][c] = p2[c][m0+m] ---
        #pragma unroll
        for (int r = 0; r < 32; r++) {
            const int c = w * 32 + r;
            s_p2[lane * 260 + c] = p2[((size_t)b * C2n + c) * Mn + m0 + lane];
        }
        __syncthreads();

        // --- 8x8 outer-product accumulation over MC m's ---
        #pragma unroll 8
        for (int m = 0; m < MC; m++) {
            const float4 a0 = *(const float4*)&s_inv[m * 64 + nt * 8];
            const float4 a1 = *(const float4*)&s_inv[m * 64 + nt * 8 + 4];
            const float4 b0 = *(const float4*)&s_p2[m * 260 + ct * 8];
            const float4 b1 = *(const float4*)&s_p2[m * 260 + ct * 8 + 4];
            const float av[8] = {a0.x, a0.y, a0.z, a0.w, a1.x, a1.y, a1.z, a1.w};
            const float bv[8] = {b0.x, b0.y, b0.z, b0.w, b1.x, b1.y, b1.z, b1.w};
            #pragma unroll
            for (int i = 0; i < 8; i++)
                #pragma unroll
                for (int j = 0; j < 8; j++)
                    acc[i][j] = fmaf(av[i], bv[j], acc[i][j]);
        }
    }

    // --- reduce denominator across the 4 m-groups ---
    __syncthreads();
    s_dsum[fmg * 64 + fn] = dsum;
    __syncthreads();
    if (tid < 64) {
        const float d = s_dsum[tid] + s_dsum[64 + tid] + s_dsum[128 + tid] + s_dsum[192 + tid];
        s_den[tid] = 1.0f / d;
    }

    // --- epilogue: scale by 1/denom, stage through smem for coalesced writes ---
    float* s_out = s_p2;   // reuse: [128][65] = 8320 floats, fits exactly
    #pragma unroll
    for (int h = 0; h < 2; h++) {
        __syncthreads();
        if ((ct >> 4) == h) {
            const int cb = ct * 8 - h * 128;
            #pragma unroll
            for (int i = 0; i < 8; i++) {
                const float wgt = s_den[nt * 8 + i];
                #pragma unroll
                for (int j = 0; j < 8; j++)
                    s_out[(cb + j) * 65 + nt * 8 + i] = acc[i][j] * wgt;
            }
        }
        __syncthreads();
        for (int idx = tid; idx < 128 * 64; idx += 256) {
            const int r = idx >> 6, n = idx & 63;
            g_interp[((size_t)b * C2n + h * 128 + r) * Nn + n_base + n] = s_out[r * 65 + n];
        }
    }
}

// ---------------- Kernel 2: fused 2-layer MLP ----------------
// grid (N/TN, B), 256 threads.
// SMEM (floats): s_x [384][64] = 24576 (reused as s_h [256][64]),
//                s_w at 24576, 8320 floats (chunk staging, padded),
//                s_b1 at 32896 (256), s_b2 at 33152 (128). Total 33280.
#define MSM_FLOATS 33280
#define MSM_BYTES  (MSM_FLOATS * 4)

__global__ __launch_bounds__(256)
void mlp_kernel(const float* __restrict__ p1,
                const float* __restrict__ W1,
                const float* __restrict__ b1,
                const float* __restrict__ W2,
                const float* __restrict__ b2,
                float* __restrict__ out)
{
    extern __shared__ float sm[];
    float* s_x  = sm;            // [CIN][64], later [H1][64] as s_h
    float* s_w  = sm + 24576;
    float* s_b1 = sm + 32896;
    float* s_b2 = sm + 33152;

    const int b   = blockIdx.y;
    const int n0  = blockIdx.x * TN;
    const int tid = threadIdx.x;
    const int lane = tid & 31, w = tid >> 5;

    s_b1[tid] = b1[tid];                 // H1 == 256 == blockDim
    if (tid < H2n) s_b2[tid] = b2[tid];

    // stage x = concat(points1, interp) tile [384][64]
    for (int idx = tid; idx < CINn * 64; idx += 256) {
        const int k = idx >> 6, n = idx & 63;
        const float v = (k < C1n)
            ? p1[((size_t)b * C1n + k) * Nn + n0 + n]
            : g_interp[((size_t)b * C2n + (k - C1n)) * Nn + n0 + n];
        s_x[idx] = v;
    }

    // ---- GEMM1: h[256][64] = relu(W1 @ x + b1) ----
    const int nt = tid & 7;    // n0t = 8*nt
    const int ot = tid >> 3;   // o0  = 8*ot
    float acc1[8][8];
    #pragma unroll
    for (int i = 0; i < 8; i++)
        #pragma unroll
        for (int j = 0; j < 8; j++) acc1[i][j] = 0.f;

    for (int kc = 0; kc < CINn / 32; kc++) {
        __syncthreads();
        #pragma unroll
        for (int r = 0; r < 32; r++) {          // stage W1 chunk transposed [k][o]
            const int o = w * 32 + r;
            s_w[lane * 260 + o] = W1[(size_t)o * CINn + kc * 32 + lane];
        }
        __syncthreads();
        #pragma unroll 8
        for (int k = 0; k < 32; k++) {
            const int kg = kc * 32 + k;
            const float4 xa = *(const float4*)&s_x[kg * 64 + nt * 8];
            const float4 xb = *(const float4*)&s_x[kg * 64 + nt * 8 + 4];
            const float4 wa = *(const float4*)&s_w[k * 260 + ot * 8];
            const float4 wb = *(const float4*)&s_w[k * 260 + ot * 8 + 4];
            const float xv[8] = {xa.x, xa.y, xa.z, xa.w, xb.x, xb.y, xb.z, xb.w};
            const float wv[8] = {wa.x, wa.y, wa.z, wa.w, wb.x, wb.y, wb.z, wb.w};
            #pragma unroll
            for (int i = 0; i < 8; i++)
                #pragma unroll
                for (int j = 0; j < 8; j++)
                    acc1[i][j] = fmaf(wv[i], xv[j], acc1[i][j]);
        }
    }

    __syncthreads();   // everyone done reading s_x
    #pragma unroll
    for (int oi = 0; oi < 8; oi++) {
        const float bias = s_b1[ot * 8 + oi];
        #pragma unroll
        for (int nj = 0; nj < 8; nj++)
            s_x[(ot * 8 + oi) * 64 + nt * 8 + nj] = fmaxf(acc1[oi][nj] + bias, 0.f);
    }

    // ---- GEMM2: out[128][64] = relu(W2 @ h + b2) ----
    const int nt2 = tid & 15;   // n = 4*nt2
    const int ot2 = tid >> 4;   // o0 = 8*ot2
    float acc2[8][4];
    #pragma unroll
    for (int i = 0; i < 8; i++)
        #pragma unroll
        for (int j = 0; j < 4; j++) acc2[i][j] = 0.f;

    for (int kc = 0; kc < H1n / 32; kc++) {
        __syncthreads();   // first iter also guards the s_h writes above
        #pragma unroll
        for (int r = 0; r < 16; r++) {          // stage W2 chunk transposed [k][o], pad 132
            const int o = w * 16 + r;
            s_w[lane * 132 + o] = W2[(size_t)o * H1n + kc * 32 + lane];
        }
        __syncthreads();
        #pragma unroll 8
        for (int k = 0; k < 32; k++) {
            const float4 ha = *(const float4*)&s_x[(kc * 32 + k) * 64 + nt2 * 4];
            const float4 wa = *(const float4*)&s_w[k * 132 + ot2 * 8];
            const float4 wb = *(const float4*)&s_w[k * 132 + ot2 * 8 + 4];
            const float hv[4] = {ha.x, ha.y, ha.z, ha.w};
            const float wv[8] = {wa.x, wa.y, wa.z, wa.w, wb.x, wb.y, wb.z, wb.w};
            #pragma unroll
            for (int i = 0; i < 8; i++)
                #pragma unroll
                for (int j = 0; j < 4; j++)
                    acc2[i][j] = fmaf(wv[i], hv[j], acc2[i][j]);
        }
    }

    #pragma unroll
    for (int oi = 0; oi < 8; oi++) {
        const int o = ot2 * 8 + oi;
        const float bias = s_b2[o];
        float4 v;
        v.x = fmaxf(acc2[oi][0] + bias, 0.f);
        v.y = fmaxf(acc2[oi][1] + bias, 0.f);
        v.z = fmaxf(acc2[oi][2] + bias, 0.f);
        v.w = fmaxf(acc2[oi][3] + bias, 0.f);
        *(float4*)&out[((size_t)b * H2n + o) * Nn + n0 + nt2 * 4] = v;
    }
}

extern "C" void kernel_launch(void* const* d_in, const int* in_sizes, int n_in,
                              void* d_out, int out_size)
{
    const float* xyz1 = (const float*)d_in[0];
    const float* xyz2 = (const float*)d_in[1];
    const float* p1   = (const float*)d_in[2];
    const float* p2   = (const float*)d_in[3];
    const float* W1   = (const float*)d_in[4];
    const float* b1   = (const float*)d_in[5];
    const float* W2   = (const float*)d_in[6];
    const float* b2   = (const float*)d_in[7];
    float* out = (float*)d_out;

    cudaFuncSetAttribute(interp_kernel, cudaFuncAttributeMaxDynamicSharedMemorySize, ISM_BYTES);
    cudaFuncSetAttribute(mlp_kernel,    cudaFuncAttributeMaxDynamicSharedMemorySize, MSM_BYTES);

    dim3 grid(Nn / TN, Bn);
    interp_kernel<<<grid, 256, ISM_BYTES>>>(xyz1, xyz2, p2);
    mlp_kernel<<<grid, 256, MSM_BYTES>>>(p1, W1, b1, W2, b2, out);
}

// round 3
// speedup vs baseline: 2.6096x; 2.6096x over previous
#include <cuda_runtime.h>
#include <cuda_bf16.h>
#include <cstdint>

// Problem constants
#define Bn   16
#define Nn   4096
#define Mn   1024
#define C1n  128
#define C2n  256
#define CINn 384
#define H1n  256
#define H2n  128

#define PITCH 144   // bytes per smem row (72 bf16): conflict-free ldmatrix

// ---------------- helpers ----------------
__device__ __forceinline__ uint32_t smem_u32(const void* p) {
    uint32_t a;
    asm("{ .reg .u64 t; cvta.to.shared.u64 t, %1; cvt.u32.u64 %0, t; }" : "=r"(a) : "l"(p));
    return a;
}
__device__ __forceinline__ void ldsm4(uint32_t* r, uint32_t addr) {
    asm volatile("ldmatrix.sync.aligned.m8n8.x4.shared.b16 {%0,%1,%2,%3}, [%4];"
        : "=r"(r[0]), "=r"(r[1]), "=r"(r[2]), "=r"(r[3]) : "r"(addr));
}
__device__ __forceinline__ void ldsm4t(uint32_t* r, uint32_t addr) {
    asm volatile("ldmatrix.sync.aligned.m8n8.x4.trans.shared.b16 {%0,%1,%2,%3}, [%4];"
        : "=r"(r[0]), "=r"(r[1]), "=r"(r[2]), "=r"(r[3]) : "r"(addr));
}
__device__ __forceinline__ void mma_bf16(float* d, const uint32_t* a, const uint32_t* b) {
    asm volatile("mma.sync.aligned.m16n8k16.row.col.f32.bf16.bf16.f32 "
        "{%0,%1,%2,%3}, {%4,%5,%6,%7}, {%8,%9}, {%0,%1,%2,%3};"
        : "+f"(d[0]), "+f"(d[1]), "+f"(d[2]), "+f"(d[3])
        : "r"(a[0]), "r"(a[1]), "r"(a[2]), "r"(a[3]), "r"(b[0]), "r"(b[1]));
}
// pack two floats: hi = truncated bf16 pair, lo = bf16 of exact remainder
__device__ __forceinline__ uint32_t bfhi2(float a, float b) {
    return __byte_perm(__float_as_uint(a), __float_as_uint(b), 0x7632);
}
__device__ __forceinline__ uint32_t bflo2(float a, float b) {
    const float la = a - __uint_as_float(__float_as_uint(a) & 0xFFFF0000u);
    const float lb = b - __uint_as_float(__float_as_uint(b) & 0xFFFF0000u);
    __nv_bfloat162 p = __floats2bfloat162_rn(la, lb);
    return *(uint32_t*)&p;
}

// scratch: interpolated features [B][C2][N] fp32
__device__ float g_interp[(size_t)Bn * C2n * Nn];

// ================= Kernel 1: interpolation via mma.sync =================
// CTA tile: 64 n-points x 256 channels, K = M = 1024 in 64-chunks, double-buffered.
// A = inv-dist weights [64 n][64 k] hi/lo   B = p2 [256 c][64 k] hi/lo
#define IA(buf, part)  ((buf) * 18432 + (part) * 9216)
#define IB(buf, part)  (36864 + (buf) * 73728 + (part) * 36864)
#define IOFF_X2  184320
#define IOFF_DS  196608
#define IOFF_DEN 197632
#define ISMB     197888

__global__ __launch_bounds__(256, 1)
void interp_tc(const float* __restrict__ xyz1,
               const float* __restrict__ xyz2,
               const float* __restrict__ p2)
{
    extern __shared__ char smc[];
    const uint32_t sb = smem_u32(smc);
    float* s_x2  = (float*)(smc + IOFF_X2);
    float* s_ds  = (float*)(smc + IOFF_DS);
    float* s_den = (float*)(smc + IOFF_DEN);

    const int tid = threadIdx.x, w = tid >> 5, lane = tid & 31;
    const int b = blockIdx.y, n0 = blockIdx.x * 64;

    for (int i = tid; i < Mn * 3; i += 256)
        s_x2[i] = xyz2[(size_t)b * Mn * 3 + i];
    __syncthreads();

    const int nf = tid & 63;        // point this thread generates weights for
    const int g  = tid >> 6;        // 16-m group within chunk
    const float px = xyz1[((size_t)b * Nn + n0 + nf) * 3 + 0];
    const float py = xyz1[((size_t)b * Nn + n0 + nf) * 3 + 1];
    const float pz = xyz1[((size_t)b * Nn + n0 + nf) * 3 + 2];
    float dsum = 0.f;

    const int mw = w & 1, cw = w >> 1;   // warp tile: 32 n x 64 c
    float acc[16][4];
    #pragma unroll
    for (int i = 0; i < 16; i++)
        #pragma unroll
        for (int j = 0; j < 4; j++) acc[i][j] = 0.f;

    // ---------- fill chunk ch into buffer ch&1 ----------
    #define FILL(ch) do {                                                          \
        const int _buf = (ch) & 1, _m0 = (ch) * 64;                                \
        _Pragma("unroll")                                                          \
        for (int j = 0; j < 2; j++) {                                              \
            const int mb = g * 16 + j * 8;                                         \
            float iv[8];                                                           \
            _Pragma("unroll")                                                      \
            for (int t = 0; t < 8; t++) {                                          \
                const int m = _m0 + mb + t;                                        \
                const float dx = px - s_x2[m * 3 + 0];                             \
                const float dy = py - s_x2[m * 3 + 1];                             \
                const float dz = pz - s_x2[m * 3 + 2];                             \
                const float d2 = fmaf(dx, dx, fmaf(dy, dy, fmaf(dz, dz, 1e-16f))); \
                iv[t] = rsqrtf(d2);                                                \
                dsum += iv[t];                                                     \
            }                                                                      \
            uint4 hv, lv;                                                          \
            hv.x = bfhi2(iv[0], iv[1]); hv.y = bfhi2(iv[2], iv[3]);                \
            hv.z = bfhi2(iv[4], iv[5]); hv.w = bfhi2(iv[6], iv[7]);                \
            lv.x = bflo2(iv[0], iv[1]); lv.y = bflo2(iv[2], iv[3]);                \
            lv.z = bflo2(iv[4], iv[5]); lv.w = bflo2(iv[6], iv[7]);                \
            *(uint4*)(smc + IA(_buf, 0) + nf * PITCH + mb * 2) = hv;               \
            *(uint4*)(smc + IA(_buf, 1) + nf * PITCH + mb * 2) = lv;               \
        }                                                                          \
        _Pragma("unroll")                                                          \
        for (int it = 0; it < 16; it++) {                                          \
            const int u = tid + it * 256;                                          \
            const int c = u >> 4, q = u & 15;                                      \
            const float4 v = *(const float4*)&p2[((size_t)b * C2n + c) * Mn + _m0 + q * 4]; \
            uint2 hv, lv;                                                          \
            hv.x = bfhi2(v.x, v.y); hv.y = bfhi2(v.z, v.w);                        \
            lv.x = bflo2(v.x, v.y); lv.y = bflo2(v.z, v.w);                        \
            *(uint2*)(smc + IB(_buf, 0) + c * PITCH + q * 8) = hv;                 \
            *(uint2*)(smc + IB(_buf, 1) + c * PITCH + q * 8) = lv;                 \
        }                                                                          \
    } while (0)

    FILL(0);
    __syncthreads();

    for (int ch = 0; ch < 16; ch++) {
        const int buf = ch & 1;
        // ---- MMA on buf ----
        #pragma unroll
        for (int kk = 0; kk < 4; kk++) {
            uint32_t ah[2][4], al[2][4];
            #pragma unroll
            for (int mt = 0; mt < 2; mt++) {
                const uint32_t row = mw * 32 + mt * 16 + (lane & 15);
                const uint32_t off = row * PITCH + kk * 32 + (lane >> 4) * 16;
                ldsm4(ah[mt], sb + IA(buf, 0) + off);
                ldsm4(al[mt], sb + IA(buf, 1) + off);
            }
            uint32_t bh[8][2], bl[8][2];
            #pragma unroll
            for (int cp = 0; cp < 4; cp++) {
                const uint32_t row = cw * 64 + cp * 16 + (lane >> 4) * 8 + (lane & 7);
                const uint32_t off = row * PITCH + kk * 32 + ((lane >> 3) & 1) * 16;
                uint32_t r[4];
                ldsm4(r, sb + IB(buf, 0) + off);
                bh[cp * 2][0] = r[0]; bh[cp * 2][1] = r[1];
                bh[cp * 2 + 1][0] = r[2]; bh[cp * 2 + 1][1] = r[3];
                ldsm4(r, sb + IB(buf, 1) + off);
                bl[cp * 2][0] = r[0]; bl[cp * 2][1] = r[1];
                bl[cp * 2 + 1][0] = r[2]; bl[cp * 2 + 1][1] = r[3];
            }
            #pragma unroll
            for (int mt = 0; mt < 2; mt++)
                #pragma unroll
                for (int ct = 0; ct < 8; ct++) {
                    mma_bf16(acc[mt * 8 + ct], ah[mt], bh[ct]);
                    mma_bf16(acc[mt * 8 + ct], ah[mt], bl[ct]);
                    mma_bf16(acc[mt * 8 + ct], al[mt], bh[ct]);
                }
        }
        // ---- fill next chunk (other buffer) ----
        if (ch < 15) FILL(ch + 1);
        __syncthreads();
    }
    #undef FILL

    // denominator
    s_ds[tid] = dsum;
    __syncthreads();
    if (tid < 64)
        s_den[tid] = 1.0f / (s_ds[tid] + s_ds[tid + 64] + s_ds[tid + 128] + s_ds[tid + 192]);
    __syncthreads();

    // epilogue: scale and store
    #pragma unroll
    for (int mt = 0; mt < 2; mt++) {
        const int nl = mw * 32 + mt * 16 + (lane >> 2);
        const float i0 = s_den[nl], i1 = s_den[nl + 8];
        #pragma unroll
        for (int ct = 0; ct < 8; ct++) {
            const int c = cw * 64 + ct * 8 + (lane & 3) * 2;
            float* d0 = &g_interp[((size_t)b * C2n + c) * Nn + n0];
            float* d1 = &g_interp[((size_t)b * C2n + c + 1) * Nn + n0];
            const float* a = acc[mt * 8 + ct];
            d0[nl]     = a[0] * i0;
            d1[nl]     = a[1] * i0;
            d0[nl + 8] = a[2] * i1;
            d1[nl + 8] = a[3] * i1;
        }
    }
}

// ================= Kernel 2: fused 2-layer MLP via mma.sync =================
// CTA: 64 n-points. GEMM1: [256 o] x [64 n] x K=384; GEMM2: [128 o] x [64 n] x K=256.
#define MW(buf, part)  ((buf) * 73728 + (part) * 36864)        // W1 chunk [256][72]
#define MX(buf, part)  (147456 + (buf) * 18432 + (part) * 9216) // x chunk [64][72]
#define MH(part)       ((part) * 36864)                         // h [256][72] (overlays MW)
#define MW2(part)      (147456 + (part) * 18432)                // W2 chunk [128][72] (overlays MX)
#define MOFF_B1  184320
#define MOFF_B2  185344
#define MSMB     185856

__global__ __launch_bounds__(256, 1)
void mlp_tc(const float* __restrict__ p1,
            const float* __restrict__ W1,
            const float* __restrict__ b1,
            const float* __restrict__ W2,
            const float* __restrict__ b2,
            float* __restrict__ out)
{
    extern __shared__ char smc[];
    const uint32_t sb = smem_u32(smc);
    float* s_b1 = (float*)(smc + MOFF_B1);
    float* s_b2 = (float*)(smc + MOFF_B2);

    const int tid = threadIdx.x, w = tid >> 5, lane = tid & 31;
    const int b = blockIdx.y, n0 = blockIdx.x * 64;

    s_b1[tid] = b1[tid];
    if (tid < H2n) s_b2[tid] = b2[tid];

    const int ow = w >> 1, nw = w & 1;   // GEMM1 warp: 64 o x 32 n

    // ---------- GEMM1 fill: W1 chunk + x chunk ----------
    #define FILL1(kc) do {                                                          \
        const int _buf = (kc) & 1;                                                  \
        _Pragma("unroll")                                                           \
        for (int it = 0; it < 16; it++) {                                           \
            const int u = tid + it * 256;                                           \
            const int o = u >> 4, q = u & 15;                                       \
            const float4 v = *(const float4*)&W1[(size_t)o * CINn + (kc) * 64 + q * 4]; \
            uint2 hv, lv;                                                           \
            hv.x = bfhi2(v.x, v.y); hv.y = bfhi2(v.z, v.w);                         \
            lv.x = bflo2(v.x, v.y); lv.y = bflo2(v.z, v.w);                         \
            *(uint2*)(smc + MW(_buf, 0) + o * PITCH + q * 8) = hv;                  \
            *(uint2*)(smc + MW(_buf, 1) + o * PITCH + q * 8) = lv;                  \
        }                                                                           \
        _Pragma("unroll")                                                           \
        for (int it = 0; it < 4; it++) {                                            \
            const int u = tid + it * 256;                                           \
            const int k = u >> 4, q = u & 15;                                       \
            const int c = (kc) * 64 + k;                                            \
            const float* src = (c < C1n)                                            \
                ? &p1[((size_t)b * C1n + c) * Nn]                                   \
                : &g_interp[((size_t)b * C2n + (c - C1n)) * Nn];                    \
            const float4 v = *(const float4*)&src[n0 + q * 4];                      \
            uint2 hv, lv;                                                           \
            hv.x = bfhi2(v.x, v.y); hv.y = bfhi2(v.z, v.w);                         \
            lv.x = bflo2(v.x, v.y); lv.y = bflo2(v.z, v.w);                         \
            *(uint2*)(smc + MX(_buf, 0) + k * PITCH + q * 8) = hv;                  \
            *(uint2*)(smc + MX(_buf, 1) + k * PITCH + q * 8) = lv;                  \
        }                                                                           \
    } while (0)

    float acc1[16][4];
    #pragma unroll
    for (int i = 0; i < 16; i++)
        #pragma unroll
        for (int j = 0; j < 4; j++) acc1[i][j] = 0.f;

    FILL1(0);
    __syncthreads();

    for (int kc = 0; kc < 6; kc++) {
        const int buf = kc & 1;
        #pragma unroll
        for (int kk = 0; kk < 4; kk++) {
            uint32_t wh[4][4], wl[4][4];
            #pragma unroll
            for (int mi = 0; mi < 4; mi++) {
                const uint32_t row = ow * 64 + mi * 16 + (lane & 15);
                const uint32_t off = row * PITCH + kk * 32 + (lane >> 4) * 16;
                ldsm4(wh[mi], sb + MW(buf, 0) + off);
                ldsm4(wl[mi], sb + MW(buf, 1) + off);
            }
            uint32_t xh[4][2], xl[4][2];
            #pragma unroll
            for (int np = 0; np < 2; np++) {
                const uint32_t row  = kk * 16 + ((lane >> 3) & 1) * 8 + (lane & 7);
                const uint32_t colb = (nw * 32 + np * 16) * 2 + (lane >> 4) * 16;
                uint32_t r[4];
                ldsm4t(r, sb + MX(buf, 0) + row * PITCH + colb);
                xh[np * 2][0] = r[0]; xh[np * 2][1] = r[1];
                xh[np * 2 + 1][0] = r[2]; xh[np * 2 + 1][1] = r[3];
                ldsm4t(r, sb + MX(buf, 1) + row * PITCH + colb);
                xl[np * 2][0] = r[0]; xl[np * 2][1] = r[1];
                xl[np * 2 + 1][0] = r[2]; xl[np * 2 + 1][1] = r[3];
            }
            #pragma unroll
            for (int mi = 0; mi < 4; mi++)
                #pragma unroll
                for (int ni = 0; ni < 4; ni++) {
                    mma_bf16(acc1[mi * 4 + ni], wh[mi], xh[ni]);
                    mma_bf16(acc1[mi * 4 + ni], wh[mi], xl[ni]);
                    mma_bf16(acc1[mi * 4 + ni], wl[mi], xh[ni]);
                }
        }
        if (kc < 5) FILL1(kc + 1);
        __syncthreads();
    }
    #undef FILL1

    // ---------- GEMM1 epilogue: relu + bias -> s_h (hi/lo), overlays MW ----------
    #pragma unroll
    for (int mi = 0; mi < 4; mi++) {
        const int o = ow * 64 + mi * 16 + (lane >> 2);
        const float bia0 = s_b1[o], bia1 = s_b1[o + 8];
        #pragma unroll
        for (int ni = 0; ni < 4; ni++) {
            const int n = nw * 32 + ni * 8 + (lane & 3) * 2;
            const float* a = acc1[mi * 4 + ni];
            const float v0 = fmaxf(a[0] + bia0, 0.f);
            const float v1 = fmaxf(a[1] + bia0, 0.f);
            const float v2 = fmaxf(a[2] + bia1, 0.f);
            const float v3 = fmaxf(a[3] + bia1, 0.f);
            *(uint32_t*)(smc + MH(0) + o * PITCH + n * 2)       = bfhi2(v0, v1);
            *(uint32_t*)(smc + MH(1) + o * PITCH + n * 2)       = bflo2(v0, v1);
            *(uint32_t*)(smc + MH(0) + (o + 8) * PITCH + n * 2) = bfhi2(v2, v3);
            *(uint32_t*)(smc + MH(1) + (o + 8) * PITCH + n * 2) = bflo2(v2, v3);
        }
    }

    // ---------- GEMM2 ----------
    const int ow2 = w >> 1;   // 32 o per warp
    float acc2[8][4];
    #pragma unroll
    for (int i = 0; i < 8; i++)
        #pragma unroll
        for (int j = 0; j < 4; j++) acc2[i][j] = 0.f;

    for (int kc = 0; kc < 4; kc++) {
        __syncthreads();   // previous compute done reading s_w2 / first: s_h written
        #pragma unroll
        for (int it = 0; it < 8; it++) {
            const int u = tid + it * 256;
            const int o = u >> 4, q = u & 15;
            const float4 v = *(const float4*)&W2[(size_t)o * H1n + kc * 64 + q * 4];
            uint2 hv, lv;
            hv.x = bfhi2(v.x, v.y); hv.y = bfhi2(v.z, v.w);
            lv.x = bflo2(v.x, v.y); lv.y = bflo2(v.z, v.w);
            *(uint2*)(smc + MW2(0) + o * PITCH + q * 8) = hv;
            *(uint2*)(smc + MW2(1) + o * PITCH + q * 8) = lv;
        }
        __syncthreads();
        #pragma unroll
        for (int kk = 0; kk < 4; kk++) {
            uint32_t wh[2][4], wl[2][4];
            #pragma unroll
            for (int mi = 0; mi < 2; mi++) {
                const uint32_t row = ow2 * 32 + mi * 16 + (lane & 15);
                const uint32_t off = row * PITCH + kk * 32 + (lane >> 4) * 16;
                ldsm4(wh[mi], sb + MW2(0) + off);
                ldsm4(wl[mi], sb + MW2(1) + off);
            }
            uint32_t hh[4][2], hl[4][2];
            #pragma unroll
            for (int np = 0; np < 2; np++) {
                const uint32_t row  = kc * 64 + kk * 16 + ((lane >> 3) & 1) * 8 + (lane & 7);
                const uint32_t colb = (nw * 32 + np * 16) * 2 + (lane >> 4) * 16;
                uint32_t r[4];
                ldsm4t(r, sb + MH(0) + row * PITCH + colb);
                hh[np * 2][0] = r[0]; hh[np * 2][1] = r[1];
                hh[np * 2 + 1][0] = r[2]; hh[np * 2 + 1][1] = r[3];
                ldsm4t(r, sb + MH(1) + row * PITCH + colb);
                hl[np * 2][0] = r[0]; hl[np * 2][1] = r[1];
                hl[np * 2 + 1][0] = r[2]; hl[np * 2 + 1][1] = r[3];
            }
            #pragma unroll
            for (int mi = 0; mi < 2; mi++)
                #pragma unroll
                for (int ni = 0; ni < 4; ni++) {
                    mma_bf16(acc2[mi * 4 + ni], wh[mi], hh[ni]);
                    mma_bf16(acc2[mi * 4 + ni], wh[mi], hl[ni]);
                    mma_bf16(acc2[mi * 4 + ni], wl[mi], hh[ni]);
                }
        }
    }

    // ---------- output ----------
    #pragma unroll
    for (int mi = 0; mi < 2; mi++) {
        const int o = ow2 * 32 + mi * 16 + (lane >> 2);
        const float bia0 = s_b2[o], bia1 = s_b2[o + 8];
        #pragma unroll
        for (int ni = 0; ni < 4; ni++) {
            const int n = n0 + nw * 32 + ni * 8 + (lane & 3) * 2;
            const float* a = acc2[mi * 4 + ni];
            float2 v0, v1;
            v0.x = fmaxf(a[0] + bia0, 0.f);
            v0.y = fmaxf(a[1] + bia0, 0.f);
            v1.x = fmaxf(a[2] + bia1, 0.f);
            v1.y = fmaxf(a[3] + bia1, 0.f);
            *(float2*)&out[((size_t)b * H2n + o) * Nn + n]     = v0;
            *(float2*)&out[((size_t)b * H2n + o + 8) * Nn + n] = v1;
        }
    }
}

extern "C" void kernel_launch(void* const* d_in, const int* in_sizes, int n_in,
                              void* d_out, int out_size)
{
    const float* xyz1 = (const float*)d_in[0];
    const float* xyz2 = (const float*)d_in[1];
    const float* p1   = (const float*)d_in[2];
    const float* p2   = (const float*)d_in[3];
    const float* W1   = (const float*)d_in[4];
    const float* b1   = (const float*)d_in[5];
    const float* W2   = (const float*)d_in[6];
    const float* b2   = (const float*)d_in[7];
    float* out = (float*)d_out;

    cudaFuncSetAttribute(interp_tc, cudaFuncAttributeMaxDynamicSharedMemorySize, ISMB);
    cudaFuncSetAttribute(mlp_tc,    cudaFuncAttributeMaxDynamicSharedMemorySize, MSMB);

    dim3 grid(Nn / 64, Bn);
    interp_tc<<<grid, 256, ISMB>>>(xyz1, xyz2, p2);
    mlp_tc<<<grid, 256, MSMB>>>(p1, W1, b1, W2, b2, out);
}